// round 14
// baseline (speedup 1.0000x reference)
#include <cuda_runtime.h>
#include <cuda_fp16.h>
#include <cuda_bf16.h>
#include <cuda_pipeline.h>

#define DPAR   1024
#define KSEL   32
#define NITER  4
#define CHUNKS 8          // 8 x float4 per lane = 32 elements/lane
#define H2N    16         // 16 half2 = 32 z values per lane
#define WPB    4          // warps per block
#define RPW    4          // rows per warp (pipelined)

__device__ __align__(16) float g_invstd[DPAR];
__device__ __align__(16) float g_nmi[DPAR];      // -mean * invstd
__device__ float g_alpha;
__device__ float g_sigma;

__global__ void prep_kernel(const float* __restrict__ ema_mean,
                            const float* __restrict__ ema_sq,
                            const float* __restrict__ log_alpha,
                            const float* __restrict__ log_sigma, int d) {
    int i = blockIdx.x * blockDim.x + threadIdx.x;
    if (i < d) {
        float m = ema_mean[i];
        float v = ema_sq[i] - m * m;
        v = fmaxf(v, 1e-6f);
        float iv = rsqrtf(v);
        g_invstd[i] = iv;
        g_nmi[i]    = -m * iv;
    }
    if (i == 0) {
        g_alpha = expf(log_alpha[0]);
        g_sigma = expf(log_sigma[0]);
    }
}

// Phi(x) = 0.5*(1+erf(x/sqrt2)) via A&S 7.1.25 3-term erfc (|eps|<=2.5e-5),
// 0.5 and 1/sqrt2 folded into coefficients.  gelu(x) = x * Phi(x).
__device__ __forceinline__ float gelu_phi(float x) {
    float ax = fabsf(x);
    float t  = __fdividef(1.0f, fmaf(0.332670553f, ax, 1.0f));
    float P  = t * fmaf(t, fmaf(t, 0.3739278f, -0.0479399f), 0.1740121f);
    float e  = exp2f(x * x * -0.72134752f);
    float he = P * e;                      // 0.5*erfc(|x|/sqrt2)
    return 0.5f + copysignf(0.5f - he, x);
}

__global__ __launch_bounds__(128, 6) void gelu_topk_kernel(
        const float4* __restrict__ x4, float4* __restrict__ out4, int rows) {
    // per-warp double buffer: 2 x 256 float4 = 8 KB/warp, 32 KB/CTA
    __shared__ float4 sx[WPB * 2 * 256];
    int wib    = threadIdx.x >> 5;
    int lane   = threadIdx.x & 31;
    int gwbase = (blockIdx.x * WPB + wib) * RPW;
    if (gwbase >= rows) return;

    const float4* s4 = reinterpret_cast<const float4*>(g_invstd) + lane;
    const float4* n4 = reinterpret_cast<const float4*>(g_nmi)    + lane;
    float4* sw0 = sx + wib * 512 + lane;                // buffer 0
    float4* sw1 = sw0 + 256;                            // buffer 1

    // ---- prologue: async-prefetch row 0 into buffer 0 ----
    {
        const float4* xr = x4 + (size_t)gwbase * (DPAR / 4) + lane;
        #pragma unroll
        for (int c = 0; c < CHUNKS; c++)
            __pipeline_memcpy_async(sw0 + c * 32, xr + c * 32, 16);
        __pipeline_commit();
    }

    #pragma unroll
    for (int r = 0; r < RPW; r++) {
        int gw = gwbase + r;
        if (gw >= rows) break;
        float4* swarp = (r & 1) ? sw1 : sw0;

        // prefetch next row into the other buffer (overlaps this row's serial work)
        if (r + 1 < RPW && gw + 1 < rows) {
            float4* swn = (r & 1) ? sw0 : sw1;
            const float4* xrn = x4 + (size_t)(gw + 1) * (DPAR / 4) + lane;
            #pragma unroll
            for (int c = 0; c < CHUNKS; c++)
                __pipeline_memcpy_async(swn + c * 32, xrn + c * 32, 16);
            __pipeline_commit();
            __pipeline_wait_prior(1);   // current row's group complete
        } else {
            __pipeline_wait_prior(0);
        }

        // ---- pass 1: z -> half2, ungated gelu overwrites x in smem ----
        __half2 z2[H2N];
        __half2 tmaxA = __float2half2_rn(0.0f);
        __half2 tmaxB = __float2half2_rn(0.0f);
        #pragma unroll
        for (int c = 0; c < CHUNKS; c++) {
            float4 xv = swarp[c * 32];
            float4 iv = __ldg(s4 + c * 32);
            float4 nm = __ldg(n4 + c * 32);
            float a  = fabsf(fmaf(xv.x, iv.x, nm.x));
            float b  = fabsf(fmaf(xv.y, iv.y, nm.y));
            float cc = fabsf(fmaf(xv.z, iv.z, nm.z));
            float dd = fabsf(fmaf(xv.w, iv.w, nm.w));
            z2[c * 2 + 0] = __floats2half2_rn(a, b);
            z2[c * 2 + 1] = __floats2half2_rn(cc, dd);
            tmaxA = __hmax2(tmaxA, z2[c * 2 + 0]);
            tmaxB = __hmax2(tmaxB, z2[c * 2 + 1]);
            float4 g;                                   // ungated GELU(x)
            g.x = xv.x * gelu_phi(xv.x);
            g.y = xv.y * gelu_phi(xv.y);
            g.z = xv.z * gelu_phi(xv.z);
            g.w = xv.w * gelu_phi(xv.w);
            swarp[c * 32] = g;                          // overwrite x with gelu
        }
        __half2 tmax2 = __hmax2(tmaxA, tmaxB);
        float tmax = fmaxf(__low2float(tmax2), __high2float(tmax2));

        // ---- bracket via REDUX on bit patterns (z >= 0) ----
        unsigned tb = __float_as_uint(tmax);
        float hi = __uint_as_float(__reduce_max_sync(0xffffffffu, tb));
        float lo = __uint_as_float(__reduce_min_sync(0xffffffffu, tb));
        float c_lo = 1024.0f, c_hi = 0.0f;

        // ---- count-based bisection, packed half2 compares + REDUX.SUM ----
        #pragma unroll
        for (int it = 0; it < NITER; ++it) {
            float T = 0.5f * (lo + hi);
            __half2 T2 = __float2half2_rn(T);
            __half2 a0 = __float2half2_rn(0.0f), a1 = a0, a2 = a0, a3 = a0;
            #pragma unroll
            for (int i = 0; i < H2N; i += 4) {
                a0 = __hadd2(a0, __hgt2(z2[i + 0], T2));
                a1 = __hadd2(a1, __hgt2(z2[i + 1], T2));
                a2 = __hadd2(a2, __hgt2(z2[i + 2], T2));
                a3 = __hadd2(a3, __hgt2(z2[i + 3], T2));
            }
            __half2 acc = __hadd2(__hadd2(a0, a1), __hadd2(a2, a3));
            int cnt = (int)(__low2float(acc) + __high2float(acc));
            cnt = __reduce_add_sync(0xffffffffu, cnt);
            if (cnt >= KSEL) { lo = T; c_lo = (float)cnt; }
            else             { hi = T; c_hi = (float)cnt; }
        }

        // ---- top-K sum: exact part above hi (count = c_hi known) ----
        __half2 hi2 = __float2half2_rn(hi);
        __half2 s0 = __float2half2_rn(0.0f), s1 = s0, s2 = s0, s3 = s0;
        #pragma unroll
        for (int i = 0; i < H2N; i += 4) {
            s0 = __hfma2(__hgt2(z2[i + 0], hi2), z2[i + 0], s0);
            s1 = __hfma2(__hgt2(z2[i + 1], hi2), z2[i + 1], s1);
            s2 = __hfma2(__hgt2(z2[i + 2], hi2), z2[i + 2], s2);
            s3 = __hfma2(__hgt2(z2[i + 3], hi2), z2[i + 3], s3);
        }
        __half2 sacc = __hadd2(__hadd2(s0, s1), __hadd2(s2, s3));
        float ssum = __low2float(sacc) + __high2float(sacc);
        int ssi = (int)(ssum * 1024.0f);
        ssi = __reduce_add_sync(0xffffffffu, ssi);
        ssum = (float)ssi * (1.0f / 1024.0f);

        float Tk = lo + (hi - lo) * (c_lo - (float)KSEL)
                        * __fdividef(1.0f, fmaxf(c_lo - c_hi, 1.0f));
        Tk = fminf(fmaxf(Tk, lo), hi);

        float surp = (ssum + ((float)KSEL - c_hi) * Tk) * (1.0f / (float)KSEL);
        float gate = 1.0f + g_alpha * tanhf(g_sigma * surp);

        // ---- pass 2: out = gate * gelu (LDS + FMUL + STG) ----
        float4* orow = out4 + (size_t)gw * (DPAR / 4) + lane;
        #pragma unroll
        for (int c = 0; c < CHUNKS; c++) {
            float4 gv = swarp[c * 32];
            float4 o;
            o.x = gate * gv.x;
            o.y = gate * gv.y;
            o.z = gate * gv.z;
            o.w = gate * gv.w;
            orow[c * 32] = o;
        }
    }
}

extern "C" void kernel_launch(void* const* d_in, const int* in_sizes, int n_in,
                              void* d_out, int out_size) {
    const float* x         = (const float*)d_in[0];
    const float* log_alpha = (const float*)d_in[1];
    const float* log_sigma = (const float*)d_in[2];
    const float* ema_mean  = (const float*)d_in[3];
    const float* ema_sq    = (const float*)d_in[4];
    float* out = (float*)d_out;

    int d    = in_sizes[3];          // 1024
    int rows = in_sizes[0] / d;      // 32768

    prep_kernel<<<(d + 255) / 256, 256>>>(ema_mean, ema_sq, log_alpha, log_sigma, d);

    int rows_per_block = WPB * RPW;  // 16
    int blocks = (rows + rows_per_block - 1) / rows_per_block;   // 2048
    gelu_topk_kernel<<<blocks, 128>>>(
        reinterpret_cast<const float4*>(x),
        reinterpret_cast<float4*>(out), rows);
}

// round 16
// speedup vs baseline: 1.2178x; 1.2178x over previous
#include <cuda_runtime.h>
#include <cuda_fp16.h>
#include <cuda_bf16.h>
#include <cuda_pipeline.h>

#define DPAR   1024
#define KSEL   32
#define NITER  4
#define CHUNKS 8          // 8 x float4 per lane = 32 elements/lane
#define H2N    16         // 16 half2 = 32 z values per lane
#define WPB    8          // warps (rows) per block

// Phi(x) = 0.5*(1+erf(x/sqrt2)) via A&S 7.1.25 3-term erfc (|eps|<=2.5e-5),
// 0.5 and 1/sqrt2 folded into coefficients.  gelu(x) = x * Phi(x).
__device__ __forceinline__ float gelu_phi(float x) {
    float ax = fabsf(x);
    float t  = __fdividef(1.0f, fmaf(0.332670553f, ax, 1.0f));
    float P  = t * fmaf(t, fmaf(t, 0.3739278f, -0.0479399f), 0.1740121f);
    float e  = exp2f(x * x * -0.72134752f);
    float he = P * e;                      // 0.5*erfc(|x|/sqrt2)
    return 0.5f + copysignf(0.5f - he, x);
}

__global__ __launch_bounds__(256, 5) void gelu_topk_kernel(
        const float4* __restrict__ x4, float4* __restrict__ out4,
        const float* __restrict__ log_alpha, const float* __restrict__ log_sigma,
        const float4* __restrict__ ema_mean4, const float4* __restrict__ ema_sq4,
        int rows) {
    __shared__ float4 sx[WPB * 256];     // 32 KB: x staged, overwritten by gelu
    __shared__ float4 siv[256];          // 4 KB: invstd
    __shared__ float4 snm[256];          // 4 KB: -mean*invstd
    int tid  = threadIdx.x;
    int wib  = tid >> 5;
    int lane = tid & 31;
    int gw   = blockIdx.x * WPB + wib;   // one warp per row

    // ---- issue x prefetch first (DRAM latency overlaps the stats compute) ----
    float4* swarp = sx + wib * 256 + lane;
    if (gw < rows) {
        const float4* xr = x4 + (size_t)gw * (DPAR / 4) + lane;
        #pragma unroll
        for (int c = 0; c < CHUNKS; c++)
            __pipeline_memcpy_async(swarp + c * 32, xr + c * 32, 16);
        __pipeline_commit();
    }

    // ---- per-CTA stats: invstd / -mean*invstd for all 1024 channels ----
    {
        float4 m = __ldg(ema_mean4 + tid);
        float4 q = __ldg(ema_sq4   + tid);
        float4 iv, nm;
        iv.x = rsqrtf(fmaxf(q.x - m.x * m.x, 1e-6f));  nm.x = -m.x * iv.x;
        iv.y = rsqrtf(fmaxf(q.y - m.y * m.y, 1e-6f));  nm.y = -m.y * iv.y;
        iv.z = rsqrtf(fmaxf(q.z - m.z * m.z, 1e-6f));  nm.z = -m.z * iv.z;
        iv.w = rsqrtf(fmaxf(q.w - m.w * m.w, 1e-6f));  nm.w = -m.w * iv.w;
        siv[tid] = iv;
        snm[tid] = nm;
    }
    float alpha = expf(__ldg(log_alpha));
    float sigma = expf(__ldg(log_sigma));
    __syncthreads();
    if (gw >= rows) return;
    __pipeline_wait_prior(0);

    // ---- pass 1: z = |x*iv + nmi| -> half2; ungated gelu overwrites x ----
    __half2 z2[H2N];
    __half2 tmaxA = __float2half2_rn(0.0f);
    __half2 tmaxB = __float2half2_rn(0.0f);
    #pragma unroll
    for (int c = 0; c < CHUNKS; c++) {
        float4 xv = swarp[c * 32];
        float4 iv = siv[c * 32 + lane];
        float4 nm = snm[c * 32 + lane];
        float a  = fabsf(fmaf(xv.x, iv.x, nm.x));
        float b  = fabsf(fmaf(xv.y, iv.y, nm.y));
        float cc = fabsf(fmaf(xv.z, iv.z, nm.z));
        float dd = fabsf(fmaf(xv.w, iv.w, nm.w));
        z2[c * 2 + 0] = __floats2half2_rn(a, b);
        z2[c * 2 + 1] = __floats2half2_rn(cc, dd);
        tmaxA = __hmax2(tmaxA, z2[c * 2 + 0]);
        tmaxB = __hmax2(tmaxB, z2[c * 2 + 1]);
        float4 g;                                    // ungated GELU(x)
        g.x = xv.x * gelu_phi(xv.x);
        g.y = xv.y * gelu_phi(xv.y);
        g.z = xv.z * gelu_phi(xv.z);
        g.w = xv.w * gelu_phi(xv.w);
        swarp[c * 32] = g;
    }
    __half2 tmax2 = __hmax2(tmaxA, tmaxB);
    float tmax = fmaxf(__low2float(tmax2), __high2float(tmax2));

    // ---- bracket via REDUX on bit patterns (z >= 0) ----
    unsigned tb = __float_as_uint(tmax);
    float hi = __uint_as_float(__reduce_max_sync(0xffffffffu, tb));
    float lo = __uint_as_float(__reduce_min_sync(0xffffffffu, tb));
    float c_lo = 1024.0f, c_hi = 0.0f;

    // ---- count-based bisection, packed half2 compares + REDUX.SUM ----
    #pragma unroll
    for (int it = 0; it < NITER; ++it) {
        float T = 0.5f * (lo + hi);
        __half2 T2 = __float2half2_rn(T);
        __half2 a0 = __float2half2_rn(0.0f), a1 = a0, a2 = a0, a3 = a0;
        #pragma unroll
        for (int i = 0; i < H2N; i += 4) {
            a0 = __hadd2(a0, __hgt2(z2[i + 0], T2));
            a1 = __hadd2(a1, __hgt2(z2[i + 1], T2));
            a2 = __hadd2(a2, __hgt2(z2[i + 2], T2));
            a3 = __hadd2(a3, __hgt2(z2[i + 3], T2));
        }
        __half2 acc = __hadd2(__hadd2(a0, a1), __hadd2(a2, a3));
        int cnt = (int)(__low2float(acc) + __high2float(acc));
        cnt = __reduce_add_sync(0xffffffffu, cnt);
        if (cnt >= KSEL) { lo = T; c_lo = (float)cnt; }
        else             { hi = T; c_hi = (float)cnt; }
    }

    // ---- top-K sum: exact part above hi (count = c_hi known) ----
    __half2 hi2 = __float2half2_rn(hi);
    __half2 s0 = __float2half2_rn(0.0f), s1 = s0, s2 = s0, s3 = s0;
    #pragma unroll
    for (int i = 0; i < H2N; i += 4) {
        s0 = __hfma2(__hgt2(z2[i + 0], hi2), z2[i + 0], s0);
        s1 = __hfma2(__hgt2(z2[i + 1], hi2), z2[i + 1], s1);
        s2 = __hfma2(__hgt2(z2[i + 2], hi2), z2[i + 2], s2);
        s3 = __hfma2(__hgt2(z2[i + 3], hi2), z2[i + 3], s3);
    }
    __half2 sacc = __hadd2(__hadd2(s0, s1), __hadd2(s2, s3));
    float ssum = __low2float(sacc) + __high2float(sacc);
    int ssi = (int)(ssum * 1024.0f);
    ssi = __reduce_add_sync(0xffffffffu, ssi);
    ssum = (float)ssi * (1.0f / 1024.0f);

    // false-position estimate of the K-th order statistic inside [lo,hi]
    float Tk = lo + (hi - lo) * (c_lo - (float)KSEL)
                    * __fdividef(1.0f, fmaxf(c_lo - c_hi, 1.0f));
    Tk = fminf(fmaxf(Tk, lo), hi);

    float surp = (ssum + ((float)KSEL - c_hi) * Tk) * (1.0f / (float)KSEL);
    float gate = 1.0f + alpha * tanhf(sigma * surp);

    // ---- pass 2: out = gate * gelu (LDS + FMUL + STG) ----
    float4* orow = out4 + (size_t)gw * (DPAR / 4) + lane;
    #pragma unroll
    for (int c = 0; c < CHUNKS; c++) {
        float4 gv = swarp[c * 32];
        float4 o;
        o.x = gate * gv.x;
        o.y = gate * gv.y;
        o.z = gate * gv.z;
        o.w = gate * gv.w;
        orow[c * 32] = o;
    }
}

extern "C" void kernel_launch(void* const* d_in, const int* in_sizes, int n_in,
                              void* d_out, int out_size) {
    const float* x         = (const float*)d_in[0];
    const float* log_alpha = (const float*)d_in[1];
    const float* log_sigma = (const float*)d_in[2];
    const float* ema_mean  = (const float*)d_in[3];
    const float* ema_sq    = (const float*)d_in[4];
    float* out = (float*)d_out;

    int d    = in_sizes[3];          // 1024
    int rows = in_sizes[0] / d;      // 32768

    int blocks = (rows + WPB - 1) / WPB;    // 4096
    gelu_topk_kernel<<<blocks, 256>>>(
        reinterpret_cast<const float4*>(x),
        reinterpret_cast<float4*>(out),
        log_alpha, log_sigma,
        reinterpret_cast<const float4*>(ema_mean),
        reinterpret_cast<const float4*>(ema_sq),
        rows);
}